// round 11
// baseline (speedup 1.0000x reference)
#include <cuda_runtime.h>

#define BB 2
#define HH 512
#define WW 512
#define HW (HH*WW)            // 262144
#define CHW ((size_t)256*HW)
#define NPIX (BB*HW)          // 524288
#define GRID 256
#define TPB 256               // 65536 threads, 8 px each; block owns 4 rows

// ---------------- device scratch (static, no allocation) ----------------
__device__ unsigned char g_alpha[2][NPIX];     // only boundary rows actually used
__device__ unsigned g_bar[8];                  // per-phase barrier counters
__device__ unsigned g_mpart[GRID][8];          // per-block {mn, mx} (32B padded)
__device__ unsigned g_spart[6][GRID][8];       // per-block {s0,s1,s2,cnt,(t0,t1,t2 @k=0)}

__device__ __forceinline__ unsigned f2ord(float f) {
    unsigned u = __float_as_uint(f);
    return (u & 0x80000000u) ? ~u : (u | 0x80000000u);
}
__device__ __forceinline__ float ord2f(unsigned u) {
    return __uint_as_float((u & 0x80000000u) ? (u ^ 0x80000000u) : ~u);
}
__device__ __forceinline__ float normq(float f, float mn, float den) {
    float v = __fmul_rn(__fdiv_rn(__fsub_rn(f, mn), den), 255.0f);
    v = floorf(v);
    return fminf(fmaxf(v, 0.0f), 255.0f);
}

// fence-free grid barrier: release arrival + acquire poll (no MEMBAR.GPU / CCTL.IVALL)
__device__ __forceinline__ void gridbar(int j) {
    __syncthreads();                       // all threads' stcg stores precede t0's release
    if (threadIdx.x == 0) {
        unsigned long long p = (unsigned long long)__cvta_generic_to_global(&g_bar[j]);
        asm volatile("red.release.gpu.global.add.u32 [%0], %1;"
                     :: "l"(p), "r"(1u) : "memory");
        unsigned v;
        do {
            asm volatile("ld.acquire.gpu.global.u32 %0, [%1];"
                         : "=r"(v) : "l"(p) : "memory");
        } while (v < GRID);
    }
    __syncthreads();
}

// ---------------- kernel 0: reset barrier counters only ----------------
__global__ void k_init() {
    if (threadIdx.x < 8) g_bar[threadIdx.x] = 0u;
}

// ---------------- whole pipeline, one persistent kernel ----------------
__global__ void __launch_bounds__(TPB, 2)
k_fused(const float* __restrict__ feat, const int* __restrict__ mask,
        float* __restrict__ out) {
    const int t    = threadIdx.x;
    const int lane = t & 31, warp = t >> 5;    // 8 warps
    const int bid  = blockIdx.x;
    const int tid  = bid * TPB + t;
    const int p0   = tid * 8;
    const int b    = p0 >> 18;
    const int r    = p0 & (HW - 1);
    const int y    = r >> 9;
    const int x0   = r & 511;
    const int ry   = t >> 6;                   // local row 0..3
    const int gbase = b << 7;                  // first block of this batch

    __shared__ unsigned char s_alpha[2][4][512];   // double-buffered alpha tile
    __shared__ unsigned s_su[7 * 8];
    __shared__ unsigned s_tot[8];
    __shared__ float    s_means[8];
    __shared__ unsigned s_u[16];

    // trimap bitmasks for this thread's 8 px
    unsigned fixmask = 0, cenmask = 0;
    {
        bool yb = (y < 51) | (y >= 461);
        bool yc = (y >= 230) & (y < 281);
        #pragma unroll
        for (int j = 0; j < 8; j++) {
            int xj = x0 + j;
            bool border = yb | (xj < 51) | (xj >= 461);
            bool center = yc & (xj >= 230) & (xj < 281);
            fixmask |= (unsigned)(border | center) << j;
            cenmask |= (unsigned)center << j;
        }
    }

    // ======== phase 1: load pixels + mask; alpha0; per-block min/max ========
    const float* fb = feat + (size_t)b * CHW;
    float f0[8], f1[8], f2[8];
    {
        float4 v;
        v = *(const float4*)(fb + r);              f0[0]=v.x; f0[1]=v.y; f0[2]=v.z; f0[3]=v.w;
        v = *(const float4*)(fb + r + 4);          f0[4]=v.x; f0[5]=v.y; f0[6]=v.z; f0[7]=v.w;
        v = *(const float4*)(fb + HW + r);         f1[0]=v.x; f1[1]=v.y; f1[2]=v.z; f1[3]=v.w;
        v = *(const float4*)(fb + HW + r + 4);     f1[4]=v.x; f1[5]=v.y; f1[6]=v.z; f1[7]=v.w;
        v = *(const float4*)(fb + 2*HW + r);       f2[0]=v.x; f2[1]=v.y; f2[2]=v.z; f2[3]=v.w;
        v = *(const float4*)(fb + 2*HW + r + 4);   f2[4]=v.x; f2[5]=v.y; f2[6]=v.z; f2[7]=v.w;
    }
    unsigned al, ah;                        // own alpha, 8 bytes packed
    {
        int4 m0 = *(const int4*)(mask + p0);
        int4 m1 = *(const int4*)(mask + p0 + 4);
        unsigned mbits =
              (m0.x==1 ? 1u:0u) | (m0.y==1 ? 2u:0u) | (m0.z==1 ? 4u:0u) | (m0.w==1 ? 8u:0u)
            | (m1.x==1 ?16u:0u) | (m1.y==1 ?32u:0u) | (m1.z==1 ?64u:0u) | (m1.w==1?128u:0u);
        unsigned abits = (fixmask & cenmask) | (~fixmask & mbits);   // per-px alpha0 bits
        al = 0; ah = 0;
        #pragma unroll
        for (int j = 0; j < 4; j++) {
            al |= ((abits >> j) & 1u) << (8*j);
            ah |= ((abits >> (j+4)) & 1u) << (8*j);
        }
        *(uint2*)&s_alpha[0][ry][x0] = make_uint2(al, ah);
        if ((ry == 0 && y > 0) || (ry == 3 && y < 511))
            __stcg((uint2*)(g_alpha[0] + p0), make_uint2(al, ah));
    }
    {
        float mnf = f0[0], mxf = f0[0];
        #pragma unroll
        for (int j = 1; j < 8; j++) { mnf = fminf(mnf, f0[j]); mxf = fmaxf(mxf, f0[j]); }
        #pragma unroll
        for (int j = 0; j < 8; j++) { mnf = fminf(mnf, f1[j]); mxf = fmaxf(mxf, f1[j]); }
        #pragma unroll
        for (int j = 0; j < 8; j++) { mnf = fminf(mnf, f2[j]); mxf = fmaxf(mxf, f2[j]); }
        unsigned mn = __reduce_min_sync(0xFFFFFFFFu, f2ord(mnf));
        unsigned mx = __reduce_max_sync(0xFFFFFFFFu, f2ord(mxf));
        if (lane == 0) { s_u[warp] = mn; s_u[8 + warp] = mx; }
        __syncthreads();
        if (warp == 0) {
            unsigned wmn = (lane < 8) ? s_u[lane]     : 0xFFFFFFFFu;
            unsigned wmx = (lane < 8) ? s_u[8 + lane] : 0u;
            wmn = __reduce_min_sync(0xFFFFFFFFu, wmn);
            wmx = __reduce_max_sync(0xFFFFFFFFu, wmx);
            if (lane == 0) {
                __stcg(&g_mpart[bid][0], wmn);
                __stcg(&g_mpart[bid][1], wmx);
            }
        }
    }
    gridbar(0);

    // ======== phase 2: gather min/max; normalize in registers + sums ========
    {
        if (warp < 2) {
            unsigned acc = warp ? 0u : 0xFFFFFFFFu;
            #pragma unroll
            for (int i = 0; i < 4; i++) {
                unsigned v = __ldcg(&g_mpart[gbase + lane + 32*i][warp]);
                acc = warp ? max(acc, v) : min(acc, v);
            }
            acc = warp ? __reduce_max_sync(0xFFFFFFFFu, acc)
                       : __reduce_min_sync(0xFFFFFFFFu, acc);
            if (lane == 0) s_u[warp] = acc;
        }
        __syncthreads();
        const float mnf = ord2f(s_u[0]);
        const float den = __fadd_rn(__fsub_rn(ord2f(s_u[1]), mnf), 1e-12f);

        float s0=0, s1=0, s2=0, cnt=0, u0=0, u1=0, u2=0;
        #pragma unroll
        for (int j = 0; j < 8; j++) {
            f0[j] = normq(f0[j], mnf, den);     // quantized values stay as floats
            f1[j] = normq(f1[j], mnf, den);
            f2[j] = normq(f2[j], mnf, den);
            unsigned abit = (j < 4) ? ((al >> (8*j)) & 1u) : ((ah >> (8*(j-4))) & 1u);
            float af = abit ? 1.0f : 0.0f;
            s0 = fmaf(f0[j], af, s0); s1 = fmaf(f1[j], af, s1);
            s2 = fmaf(f2[j], af, s2); cnt += af;
            u0 += f0[j]; u1 += f1[j]; u2 += f2[j];
        }
        unsigned v[7] = {(unsigned)s0, (unsigned)s1, (unsigned)s2, (unsigned)cnt,
                         (unsigned)u0, (unsigned)u1, (unsigned)u2};
        #pragma unroll
        for (int j = 0; j < 7; j++) {
            unsigned w = __reduce_add_sync(0xFFFFFFFFu, v[j]);
            if (lane == 0) s_su[j*8 + warp] = w;
        }
        __syncthreads();
        if (warp == 0) {
            unsigned accs[7];
            #pragma unroll
            for (int j = 0; j < 7; j++) {
                unsigned acc = (lane < 8) ? s_su[j*8 + lane] : 0u;
                accs[j] = __reduce_add_sync(0xFFFFFFFFu, acc);
            }
            if (lane < 7) __stcg(&g_spart[0][bid][lane], accs[lane]);
        }
    }
    gridbar(1);

    // ======== phase 3: 5 ICM iterations (rolled loop, small I$ footprint) ========
    #pragma unroll 1
    for (int k = 0; k < 5; k++) {
        const int cur = k & 1, nxt = cur ^ 1;
        const bool last = (k == 4);

        // parallel gather: warp w sums 128 per-block partials of value w
        if (warp < 7) {
            const int kk = (warp < 4) ? k : 0;    // totals live in k=0 slot
            unsigned acc = 0;
            #pragma unroll
            for (int i = 0; i < 4; i++)
                acc += __ldcg(&g_spart[kk][gbase + lane + 32*i][warp]);
            acc = __reduce_add_sync(0xFFFFFFFFu, acc);
            if (lane == 0) s_tot[warp] = acc;
        }
        // neighbor fetch overlapped with gather (s_alpha[cur] synced last iter)
        uint2 up, dn;
        if (ry == 0) up = (y == 0)   ? make_uint2(al, ah)
                                     : __ldcg((const uint2*)(g_alpha[cur] + p0 - WW));
        else         up = *(const uint2*)&s_alpha[cur][ry-1][x0];
        if (ry == 3) dn = (y == 511) ? make_uint2(al, ah)
                                     : __ldcg((const uint2*)(g_alpha[cur] + p0 + WW));
        else         dn = *(const uint2*)&s_alpha[cur][ry+1][x0];
        unsigned lft = (x0 == 0)   ? (al & 255u)         : (unsigned)s_alpha[cur][ry][x0-1];
        unsigned rgt = (x0 == 504) ? ((ah >> 24) & 255u) : (unsigned)s_alpha[cur][ry][x0+8];
        __syncthreads();
        if (t < 6) {
            float cntf = (float)s_tot[3];
            if (t < 3) {
                s_means[t] = __fdiv_rn((float)s_tot[t], __fadd_rn(cntf, 1e-6f));
            } else {
                unsigned j = t - 3;
                s_means[t] = __fdiv_rn((float)(s_tot[4 + j] - s_tot[j]),
                                       __fadd_rn(__fsub_rn((float)HW, cntf), 1e-6f));
            }
        }
        __syncthreads();
        const float fm0 = s_means[0], fm1 = s_means[1], fm2 = s_means[2];
        const float bm0 = s_means[3], bm1 = s_means[4], bm2 = s_means[5];

        // byte-SIMD neighbor counts (n per byte in 0..4)
        unsigned lv_lo = (al << 8) | lft;
        unsigned lv_hi = (ah << 8) | (al >> 24);
        unsigned rv_lo = (al >> 8) | (ah << 24);
        unsigned rv_hi = (ah >> 8) | (rgt << 24);
        unsigned n_lo = __vadd4(__vadd4(up.x, dn.x), __vadd4(lv_lo, rv_lo));
        unsigned n_hi = __vadd4(__vadd4(up.y, dn.y), __vadd4(lv_hi, rv_hi));

        unsigned nl = 0, nh = 0;
        float s0 = 0, s1 = 0, s2 = 0, cnt = 0;
        #pragma unroll
        for (int j = 0; j < 8; j++) {
            float i0 = f0[j], i1 = f1[j], i2 = f2[j];
            int n = (int)(((j < 4 ? n_lo : n_hi) >> (8 * (j & 3))) & 255u);
            float pw = (float)(25 * n - 50);       // == 50*(2*(n/4)-1) exactly

            float d0 = __fsub_rn(i0, fm0), d1 = __fsub_rn(i1, fm1), d2 = __fsub_rn(i2, fm2);
            float dfg = __fadd_rn(__fadd_rn(__fmul_rn(d0, d0), __fmul_rn(d1, d1)),
                                  __fmul_rn(d2, d2));
            float e0 = __fsub_rn(i0, bm0), e1 = __fsub_rn(i1, bm1), e2 = __fsub_rn(i2, bm2);
            float dbg = __fadd_rn(__fadd_rn(__fmul_rn(e0, e0), __fmul_rn(e1, e1)),
                                  __fmul_rn(e2, e2));
            float score = __fadd_rn(__fsub_rn(dbg, dfg), pw);

            bool fg = ((fixmask >> j) & 1u) ? (((cenmask >> j) & 1u) != 0u)
                                            : (score > 0.0f);
            unsigned a = fg ? 1u : 0u;
            float af  = fg ? 1.0f : 0.0f;
            if (j < 4) nl |= a << (8*j); else nh |= a << (8*(j-4));
            s0 = fmaf(i0, af, s0); s1 = fmaf(i1, af, s1);
            s2 = fmaf(i2, af, s2); cnt += af;
        }
        al = nl; ah = nh;

        if (!last) {
            *(uint2*)&s_alpha[nxt][ry][x0] = make_uint2(nl, nh);
            if ((ry == 0 && y > 0) || (ry == 3 && y < 511))
                __stcg((uint2*)(g_alpha[nxt] + p0), make_uint2(nl, nh));

            unsigned v[4] = {(unsigned)s0, (unsigned)s1, (unsigned)s2, (unsigned)cnt};
            #pragma unroll
            for (int j = 0; j < 4; j++) {
                unsigned w = __reduce_add_sync(0xFFFFFFFFu, v[j]);
                if (lane == 0) s_su[j*8 + warp] = w;
            }
            __syncthreads();
            if (warp == 0) {
                unsigned accs[4];
                #pragma unroll
                for (int j = 0; j < 4; j++) {
                    unsigned acc = (lane < 8) ? s_su[j*8 + lane] : 0u;
                    accs[j] = __reduce_add_sync(0xFFFFFFFFu, acc);
                }
                if (lane < 4) __stcg(&g_spart[k+1][bid][lane], accs[lane]);
            }
            gridbar(2 + k);
        } else {
            *(float4*)(out + p0)     = make_float4((float)(nl & 1u),
                                                   (float)((nl >> 8) & 1u),
                                                   (float)((nl >> 16) & 1u),
                                                   (float)((nl >> 24) & 1u));
            *(float4*)(out + p0 + 4) = make_float4((float)(nh & 1u),
                                                   (float)((nh >> 8) & 1u),
                                                   (float)((nh >> 16) & 1u),
                                                   (float)((nh >> 24) & 1u));
        }
    }
}

extern "C" void kernel_launch(void* const* d_in, const int* in_sizes, int n_in,
                              void* d_out, int out_size) {
    const float* feat = (const float*)d_in[0];
    const int*   mask = (const int*)d_in[1];
    float*       out  = (float*)d_out;

    k_init<<<1, 32>>>();
    k_fused<<<GRID, TPB>>>(feat, mask, out);
}